// round 1
// baseline (speedup 1.0000x reference)
#include <cuda_runtime.h>
#include <math.h>
#include <float.h>

// ---------------------------------------------------------------------------
// Informer_42193758716151 — fp32 baseline
// B=4, L=1024, D_MODEL=512, N_HEADS=8, HEAD_DIM=64, N_LAYERS=2, D_FF=2048,
// SAMPLE_K=35 (= n_top), N_CLASSES=10
// ---------------------------------------------------------------------------

#define B_   4
#define L_   1024
#define DM   512
#define NH   8
#define HD   64
#define DFF  2048
#define SK   35
#define NTOK (B_*L_)   // 4096

// Scratch (device globals: allocation-free rule)
__device__ float g_x   [NTOK*DM];
__device__ float g_tmp [NTOK*DM];
__device__ float g_q   [NTOK*DM];
__device__ float g_k   [NTOK*DM];
__device__ float g_v   [NTOK*DM];
__device__ float g_ctx [NTOK*DM];
__device__ float g_ff  [NTOK*DFF];
__device__ float g_M   [B_*NH*L_];
__device__ int   g_top [B_*NH*SK];
__device__ float g_vmean[B_*NH*HD];
__device__ float g_poolp[B_*8*DM];   // pooling partials (8 chunks of 128 rows)
__device__ float g_pool [B_*DM];

// ---------------------------------------------------------------------------
// Embedding + positional encoding:
// x[b,l,d] = sum_k src[b,l,k]*Wemb[k,d] + bemb[d] + pe(l,d)
// ---------------------------------------------------------------------------
__global__ void embed_kernel(const float* __restrict__ src,
                             const float* __restrict__ Wemb,
                             const float* __restrict__ bemb) {
    int row = blockIdx.x;            // token index 0..4095
    int l   = row & (L_-1);
    int d   = threadIdx.x;           // 512 threads
    __shared__ float s[32];
    if (d < 32) s[d] = src[row*32 + d];
    __syncthreads();
    float acc = bemb[d];
    #pragma unroll
    for (int k = 0; k < 32; k++) acc += s[k] * Wemb[k*DM + d];
    int i2 = d & ~1;
    float div = expf(-(float)i2 * (9.210340371976184f / 512.0f)); // ln(10000)/512
    float ang = (float)l * div;
    acc += (d & 1) ? cosf(ang) : sinf(ang);
    g_x[row*DM + d] = acc;
}

// ---------------------------------------------------------------------------
// GEMM: C[M,N] = A[M,K] @ W[K,N] + bias (+resid) (+exact GELU)
// M = 4096 (grid.y*128), N multiple of 64, K multiple of 16.
// Tile 128x64x16, 256 threads, 8x4 register blocking.
// ---------------------------------------------------------------------------
template<bool GELU>
__global__ void gemm_kernel(const float* __restrict__ A,
                            const float* __restrict__ W,
                            const float* __restrict__ bias,
                            const float* __restrict__ resid,
                            float* __restrict__ C,
                            int N, int K) {
    const int BM = 128, BN = 64, BK = 16;
    __shared__ float As[BK][BM];
    __shared__ float Bs[BK][BN];

    int tid = threadIdx.x;            // 256
    int tx  = tid & 15;               // 0..15 -> n
    int ty  = tid >> 4;               // 0..15 -> m
    int m0  = blockIdx.y * BM;
    int n0  = blockIdx.x * BN;

    float acc[8][4];
    #pragma unroll
    for (int i = 0; i < 8; i++)
        #pragma unroll
        for (int j = 0; j < 4; j++) acc[i][j] = 0.f;

    for (int k0 = 0; k0 < K; k0 += BK) {
        // Load A tile: 128x16 = 2048 floats, 2 float4 per thread, transposed store
        #pragma unroll
        for (int it = 0; it < 2; it++) {
            int f  = tid + it*256;        // float4 index 0..511
            int m  = f >> 2;              // 0..127
            int kc = (f & 3) << 2;        // 0,4,8,12
            float4 v = *(const float4*)&A[(size_t)(m0+m)*K + k0 + kc];
            As[kc+0][m] = v.x; As[kc+1][m] = v.y;
            As[kc+2][m] = v.z; As[kc+3][m] = v.w;
        }
        // Load W tile: 16x64 = 1024 floats, 1 float4 per thread
        {
            int kr = tid >> 4;            // 0..15
            int nc = (tid & 15) << 2;     // 0..60
            *(float4*)&Bs[kr][nc] = *(const float4*)&W[(size_t)(k0+kr)*N + n0 + nc];
        }
        __syncthreads();

        #pragma unroll
        for (int kk = 0; kk < BK; kk++) {
            float4 a0 = *(float4*)&As[kk][ty*8];
            float4 a1 = *(float4*)&As[kk][ty*8+4];
            float4 b0 = *(float4*)&Bs[kk][tx*4];
            float a[8] = {a0.x,a0.y,a0.z,a0.w,a1.x,a1.y,a1.z,a1.w};
            float b[4] = {b0.x,b0.y,b0.z,b0.w};
            #pragma unroll
            for (int i = 0; i < 8; i++)
                #pragma unroll
                for (int j = 0; j < 4; j++)
                    acc[i][j] += a[i]*b[j];
        }
        __syncthreads();
    }

    #pragma unroll
    for (int i = 0; i < 8; i++) {
        int m = m0 + ty*8 + i;
        #pragma unroll
        for (int j = 0; j < 4; j++) {
            int n = n0 + tx*4 + j;
            float v = acc[i][j] + bias[n];
            if (resid) v += resid[(size_t)m*N + n];
            if (GELU)  v = 0.5f*v*(1.0f + erff(v*0.70710678118654752f));
            C[(size_t)m*N + n] = v;
        }
    }
}

// ---------------------------------------------------------------------------
// Sampled sparsity measure: M[b,h,i] = max_j(q_i . k_{idx[i,j]}) - mean_j(...)
// One warp per (b,h,i).
// ---------------------------------------------------------------------------
__global__ void sampleM_kernel(const int* __restrict__ idxs) {
    int w    = (blockIdx.x * blockDim.x + threadIdx.x) >> 5;
    int lane = threadIdx.x & 31;
    if (w >= B_*NH*L_) return;
    int i = w & (L_-1);
    int h = (w >> 10) & (NH-1);
    int b = w >> 13;
    const float* Qrow = &g_q[(size_t)(b*L_ + i)*DM + h*HD];
    float qa = Qrow[lane], qb = Qrow[lane+32];
    float mx = -FLT_MAX, sm = 0.f;
    for (int j = 0; j < SK; j++) {
        int s = idxs[i*SK + j];
        const float* Krow = &g_k[(size_t)(b*L_ + s)*DM + h*HD];
        float p = qa*Krow[lane] + qb*Krow[lane+32];
        #pragma unroll
        for (int o = 16; o > 0; o >>= 1) p += __shfl_xor_sync(0xffffffffu, p, o);
        mx = fmaxf(mx, p);
        sm += p;
    }
    if (lane == 0) g_M[(b*NH+h)*L_ + i] = mx - sm * (1.0f/SK);
}

// ---------------------------------------------------------------------------
// top-35 of M over L (exact, ties -> lowest index, matching lax.top_k set)
// One block per (b,h).
// ---------------------------------------------------------------------------
__global__ void topk_kernel() {
    int bh = blockIdx.x;              // 0..31
    int t  = threadIdx.x;             // 256
    __shared__ float sv[L_];
    __shared__ float rv[256];
    __shared__ int   ri[256];
    #pragma unroll
    for (int r = 0; r < 4; r++) sv[t + r*256] = g_M[bh*L_ + t + r*256];
    __syncthreads();
    for (int iter = 0; iter < SK; iter++) {
        float bv = -FLT_MAX; int bi = L_;
        #pragma unroll
        for (int r = 0; r < 4; r++) {
            int idx = t + r*256;
            float v = sv[idx];
            if (v > bv || (v == bv && idx < bi)) { bv = v; bi = idx; }
        }
        rv[t] = bv; ri[t] = bi;
        __syncthreads();
        for (int s = 128; s > 0; s >>= 1) {
            if (t < s) {
                if (rv[t+s] > rv[t] || (rv[t+s] == rv[t] && ri[t+s] < ri[t])) {
                    rv[t] = rv[t+s]; ri[t] = ri[t+s];
                }
            }
            __syncthreads();
        }
        if (t == 0) { g_top[bh*SK + iter] = ri[0]; sv[ri[0]] = -FLT_MAX; }
        __syncthreads();
    }
}

// ---------------------------------------------------------------------------
// V mean over L per (b,h). Block = 512 threads (8 partial chunks x 64 dims).
// ---------------------------------------------------------------------------
__global__ void vmean_kernel() {
    int bh = blockIdx.x;
    int b = bh / NH, h = bh % NH;
    int t = threadIdx.x;
    int e = t & 63, r = t >> 6;       // r in 0..7
    float acc = 0.f;
    for (int l = r*128; l < r*128 + 128; l++)
        acc += g_v[(size_t)(b*L_+l)*DM + h*HD + e];
    __shared__ float sh[512];
    sh[t] = acc;
    __syncthreads();
    if (t < 64) {
        float s = 0.f;
        #pragma unroll
        for (int rr = 0; rr < 8; rr++) s += sh[t + rr*64];
        g_vmean[bh*HD + t] = s * (1.0f/L_);
    }
}

// Fill context with broadcast V-mean (attn kernel scatters on top of this)
__global__ void fillctx_kernel() {
    int row = blockIdx.x;             // 4096
    int d   = threadIdx.x;            // 512
    int b = row >> 10;
    int h = d >> 6, e = d & 63;
    g_ctx[(size_t)row*DM + d] = g_vmean[(b*NH+h)*HD + e];
}

// ---------------------------------------------------------------------------
// Full attention for the 35 selected queries; scatter into g_ctx.
// One block (128 threads) per (b,h,u).
// ---------------------------------------------------------------------------
__global__ void attn_kernel() {
    int u = blockIdx.x % SK;
    int h = (blockIdx.x / SK) % NH;
    int b =  blockIdx.x / (SK*NH);
    int t = threadIdx.x;              // 128
    __shared__ float sq[HD];
    __shared__ float sc[L_];
    __shared__ float red[128];

    int qi = g_top[(b*NH+h)*SK + u];
    if (t < HD) sq[t] = g_q[(size_t)(b*L_+qi)*DM + h*HD + t];
    __syncthreads();

    float ls[8];
    float lmax = -FLT_MAX;
    #pragma unroll
    for (int r = 0; r < 8; r++) {
        int s = t + r*128;
        const float* Kr = &g_k[(size_t)(b*L_+s)*DM + h*HD];
        float acc = 0.f;
        #pragma unroll
        for (int e = 0; e < HD; e++) acc += sq[e]*Kr[e];
        acc *= 0.125f;                // 1/sqrt(64)
        ls[r] = acc;
        lmax = fmaxf(lmax, acc);
    }
    red[t] = lmax; __syncthreads();
    for (int s = 64; s > 0; s >>= 1) { if (t < s) red[t] = fmaxf(red[t], red[t+s]); __syncthreads(); }
    float mx = red[0];
    __syncthreads();

    float lsum = 0.f;
    #pragma unroll
    for (int r = 0; r < 8; r++) {
        float e = expf(ls[r] - mx);
        sc[t + r*128] = e;
        lsum += e;
    }
    red[t] = lsum; __syncthreads();
    for (int s = 64; s > 0; s >>= 1) { if (t < s) red[t] += red[t+s]; __syncthreads(); }
    float inv = 1.0f / red[0];
    __syncthreads();

    if (t < HD) {
        float acc = 0.f;
        for (int s = 0; s < L_; s++)
            acc += sc[s] * g_v[(size_t)(b*L_+s)*DM + h*HD + t];
        g_ctx[(size_t)(b*L_+qi)*DM + h*HD + t] = acc * inv;
    }
}

// ---------------------------------------------------------------------------
// LayerNorm over last dim (512). One block (256 threads) per row.
// ---------------------------------------------------------------------------
__global__ void ln_kernel(const float* __restrict__ in, float* __restrict__ out,
                          const float* __restrict__ g, const float* __restrict__ be) {
    int row = blockIdx.x;
    int t   = threadIdx.x;            // 256
    float v0 = in[(size_t)row*DM + t];
    float v1 = in[(size_t)row*DM + t + 256];
    __shared__ float red[256];
    red[t] = v0 + v1; __syncthreads();
    for (int s = 128; s > 0; s >>= 1) { if (t < s) red[t] += red[t+s]; __syncthreads(); }
    float mean = red[0] * (1.0f/DM);
    __syncthreads();
    float d0 = v0 - mean, d1 = v1 - mean;
    red[t] = d0*d0 + d1*d1; __syncthreads();
    for (int s = 128; s > 0; s >>= 1) { if (t < s) red[t] += red[t+s]; __syncthreads(); }
    float rstd = rsqrtf(red[0] * (1.0f/DM) + 1e-5f);
    out[(size_t)row*DM + t]       = d0*rstd*g[t]     + be[t];
    out[(size_t)row*DM + t + 256] = d1*rstd*g[t+256] + be[t+256];
}

// ---------------------------------------------------------------------------
// Mean pool over L (two stage for parallelism/determinism) + classifier
// ---------------------------------------------------------------------------
__global__ void pool1_kernel() {       // grid (4,8), block 512
    int b = blockIdx.x, r = blockIdx.y;
    int d = threadIdx.x;
    float acc = 0.f;
    for (int l = r*128; l < r*128 + 128; l++)
        acc += g_tmp[(size_t)(b*L_+l)*DM + d];
    g_poolp[(b*8 + r)*DM + d] = acc;
}

__global__ void pool2_kernel() {       // grid 4, block 512
    int b = blockIdx.x;
    int d = threadIdx.x;
    float acc = 0.f;
    #pragma unroll
    for (int r = 0; r < 8; r++) acc += g_poolp[(b*8 + r)*DM + d];
    g_pool[b*DM + d] = acc * (1.0f/L_);
}

__global__ void cls_kernel(const float* __restrict__ Wc,
                           const float* __restrict__ bc,
                           float* __restrict__ out) {
    int t = threadIdx.x;
    if (t >= B_*10) return;
    int b = t / 10, c = t % 10;
    float acc = bc[c];
    for (int d = 0; d < DM; d++) acc += g_pool[b*DM + d] * Wc[d*10 + c];
    out[b*10 + c] = acc;
}

// ---------------------------------------------------------------------------
// Launch
// ---------------------------------------------------------------------------
extern "C" void kernel_launch(void* const* d_in, const int* in_sizes, int n_in,
                              void* d_out, int out_size) {
    const float* src   = (const float*)d_in[0];
    const int*   idxs  = (const int*)  d_in[1];
    const float* Wemb  = (const float*)d_in[2];
    const float* bemb  = (const float*)d_in[3];
    const float* Wq    = (const float*)d_in[4];
    const float* bq    = (const float*)d_in[5];
    const float* Wk    = (const float*)d_in[6];
    const float* bk    = (const float*)d_in[7];
    const float* Wv    = (const float*)d_in[8];
    const float* bv    = (const float*)d_in[9];
    const float* Wo    = (const float*)d_in[10];
    const float* bo    = (const float*)d_in[11];
    const float* g1    = (const float*)d_in[12];
    const float* beta1 = (const float*)d_in[13];
    const float* W1    = (const float*)d_in[14];
    const float* bf1   = (const float*)d_in[15];
    const float* W2    = (const float*)d_in[16];
    const float* bf2   = (const float*)d_in[17];
    const float* g2    = (const float*)d_in[18];
    const float* beta2 = (const float*)d_in[19];
    const float* gf    = (const float*)d_in[20];
    const float* betaf = (const float*)d_in[21];
    const float* Wc    = (const float*)d_in[22];
    const float* bc    = (const float*)d_in[23];

    void *px_, *ptmp_, *pq_, *pk_, *pv_, *pctx_, *pff_;
    cudaGetSymbolAddress(&px_,   g_x);
    cudaGetSymbolAddress(&ptmp_, g_tmp);
    cudaGetSymbolAddress(&pq_,   g_q);
    cudaGetSymbolAddress(&pk_,   g_k);
    cudaGetSymbolAddress(&pv_,   g_v);
    cudaGetSymbolAddress(&pctx_, g_ctx);
    cudaGetSymbolAddress(&pff_,  g_ff);
    float* px   = (float*)px_;
    float* ptmp = (float*)ptmp_;
    float* pq   = (float*)pq_;
    float* pk   = (float*)pk_;
    float* pv   = (float*)pv_;
    float* pctx = (float*)pctx_;
    float* pff  = (float*)pff_;

    embed_kernel<<<NTOK, 512>>>(src, Wemb, bemb);

    for (int l = 0; l < 2; l++) {
        const float* Wq_l = Wq + (size_t)l*DM*DM;
        const float* Wk_l = Wk + (size_t)l*DM*DM;
        const float* Wv_l = Wv + (size_t)l*DM*DM;
        const float* Wo_l = Wo + (size_t)l*DM*DM;
        const float* W1_l = W1 + (size_t)l*DM*DFF;
        const float* W2_l = W2 + (size_t)l*DFF*DM;

        dim3 gDM(DM/64, NTOK/128);      // (8, 32)
        dim3 gFF(DFF/64, NTOK/128);     // (32, 32)

        gemm_kernel<false><<<gDM, 256>>>(px, Wq_l, bq + l*DM, nullptr, pq, DM, DM);
        gemm_kernel<false><<<gDM, 256>>>(px, Wk_l, bk + l*DM, nullptr, pk, DM, DM);
        gemm_kernel<false><<<gDM, 256>>>(px, Wv_l, bv + l*DM, nullptr, pv, DM, DM);

        sampleM_kernel<<<(B_*NH*L_)/4, 128>>>(idxs + (size_t)l*L_*SK);
        topk_kernel<<<B_*NH, 256>>>();
        vmean_kernel<<<B_*NH, 512>>>();
        fillctx_kernel<<<NTOK, 512>>>();
        attn_kernel<<<B_*NH*SK, 128>>>();

        gemm_kernel<false><<<gDM, 256>>>(pctx, Wo_l, bo + l*DM, px, ptmp, DM, DM);
        ln_kernel<<<NTOK, 256>>>(ptmp, px, g1 + l*DM, beta1 + l*DM);

        gemm_kernel<true ><<<gFF, 256>>>(px, W1_l, bf1 + l*DFF, nullptr, pff, DFF, DM);
        gemm_kernel<false><<<gDM, 256>>>(pff, W2_l, bf2 + l*DM, px, ptmp, DM, DFF);
        ln_kernel<<<NTOK, 256>>>(ptmp, px, g2 + l*DM, beta2 + l*DM);
    }

    ln_kernel<<<NTOK, 256>>>(px, ptmp, gf, betaf);
    pool1_kernel<<<dim3(B_, 8), 512>>>();
    pool2_kernel<<<B_, 512>>>();
    cls_kernel<<<1, 64>>>(Wc, bc, (float*)d_out);
}

// round 2
// speedup vs baseline: 2.3102x; 2.3102x over previous
#include <cuda_runtime.h>
#include <math.h>
#include <float.h>
#include <stdint.h>

// ---------------------------------------------------------------------------
// Informer: B=4, L=1024, DM=512, NH=8, HD=64, DFF=2048, SK=35, 2 layers
// ---------------------------------------------------------------------------
#define B_   4
#define L_   1024
#define DM   512
#define NH   8
#define HD   64
#define DFF  2048
#define SK   35
#define NTOK (B_*L_)   // 4096

__device__ float g_x   [NTOK*DM];
__device__ float g_tmp [NTOK*DM];
__device__ float g_q   [NTOK*DM];
__device__ float g_k   [NTOK*DM];
__device__ float g_v   [NTOK*DM];
__device__ float g_ctx [NTOK*DM];
__device__ float g_ff  [NTOK*DFF];
__device__ float g_M   [B_*NH*L_];
__device__ int   g_top [B_*NH*SK];
__device__ float g_poolp[B_*8*DM];
__device__ float g_pool [B_*DM];

// ---------------------------------------------------------------------------
__device__ __forceinline__ float to_tf32(float x) {
    uint32_t u;
    asm("cvt.rna.tf32.f32 %0, %1;" : "=r"(u) : "f"(x));
    return __uint_as_float(u);
}

__device__ __forceinline__ void mma_tf32(float* c, const uint32_t* a,
                                         uint32_t b0, uint32_t b1) {
    asm volatile(
        "mma.sync.aligned.m16n8k8.row.col.f32.tf32.tf32.f32 "
        "{%0,%1,%2,%3},{%4,%5,%6,%7},{%8,%9},{%0,%1,%2,%3};"
        : "+f"(c[0]), "+f"(c[1]), "+f"(c[2]), "+f"(c[3])
        : "r"(a[0]), "r"(a[1]), "r"(a[2]), "r"(a[3]), "r"(b0), "r"(b1));
}

// ---------------------------------------------------------------------------
// Embedding + positional encoding
// ---------------------------------------------------------------------------
__global__ void embed_kernel(const float* __restrict__ src,
                             const float* __restrict__ Wemb,
                             const float* __restrict__ bemb) {
    int row = blockIdx.x;
    int l   = row & (L_-1);
    int d   = threadIdx.x;
    __shared__ float s[32];
    if (d < 32) s[d] = src[row*32 + d];
    __syncthreads();
    float acc = bemb[d];
    #pragma unroll
    for (int k = 0; k < 32; k++) acc += s[k] * Wemb[k*DM + d];
    int i2 = d & ~1;
    float div = expf(-(float)i2 * (9.210340371976184f / 512.0f));
    float ang = (float)l * div;
    acc += (d & 1) ? cosf(ang) : sinf(ang);
    g_x[row*DM + d] = acc;
}

// ---------------------------------------------------------------------------
// tf32 tensor-core GEMM: C[M,N] = A[M,K] @ W[K,N] + bias (+resid) (+GELU)
// Block tile 128x128x16, 256 threads (8 warps, 4x2), double-buffered smem.
// ---------------------------------------------------------------------------
template<bool GELU>
__global__ void __launch_bounds__(256, 2)
gemm_tc(const float* __restrict__ A, const float* __restrict__ W,
        const float* __restrict__ bias, const float* __restrict__ resid,
        float* __restrict__ C, int N, int K) {
    __shared__ float As[2][16][136];   // [k][m], pad 8 -> conflict-free frags
    __shared__ float Bs[2][16][136];   // [k][n]

    const int tid = threadIdx.x;
    const int w    = tid >> 5;
    const int lane = tid & 31;
    const int grp  = lane >> 2;        // 0..7
    const int qd   = lane & 3;         // 0..3
    const int warp_m = (w & 3) * 32;
    const int warp_n = (w >> 2) * 64;
    const int m0 = blockIdx.y * 128;
    const int n0 = blockIdx.x * 128;

    // staging indices
    const int am  = tid >> 2;          // A: rows tid>>2 and +64
    const int akc = (tid & 3) << 2;
    const int bkr = tid >> 5;          // B: k rows tid>>5 and +8
    const int bnc = (tid & 31) << 2;

    float acc[2][8][4];
    #pragma unroll
    for (int mi = 0; mi < 2; mi++)
        #pragma unroll
        for (int ni = 0; ni < 8; ni++)
            #pragma unroll
            for (int j = 0; j < 4; j++) acc[mi][ni][j] = 0.f;

    const int nt = K >> 4;

    // prologue: tile 0
    {
        float4 ra0 = *(const float4*)&A[(size_t)(m0+am)*K + akc];
        float4 ra1 = *(const float4*)&A[(size_t)(m0+am+64)*K + akc];
        float4 rb0 = *(const float4*)&W[(size_t)bkr*N + n0 + bnc];
        float4 rb1 = *(const float4*)&W[(size_t)(bkr+8)*N + n0 + bnc];
        As[0][akc+0][am] = to_tf32(ra0.x); As[0][akc+1][am] = to_tf32(ra0.y);
        As[0][akc+2][am] = to_tf32(ra0.z); As[0][akc+3][am] = to_tf32(ra0.w);
        As[0][akc+0][am+64] = to_tf32(ra1.x); As[0][akc+1][am+64] = to_tf32(ra1.y);
        As[0][akc+2][am+64] = to_tf32(ra1.z); As[0][akc+3][am+64] = to_tf32(ra1.w);
        Bs[0][bkr][bnc+0] = to_tf32(rb0.x); Bs[0][bkr][bnc+1] = to_tf32(rb0.y);
        Bs[0][bkr][bnc+2] = to_tf32(rb0.z); Bs[0][bkr][bnc+3] = to_tf32(rb0.w);
        Bs[0][bkr+8][bnc+0] = to_tf32(rb1.x); Bs[0][bkr+8][bnc+1] = to_tf32(rb1.y);
        Bs[0][bkr+8][bnc+2] = to_tf32(rb1.z); Bs[0][bkr+8][bnc+3] = to_tf32(rb1.w);
    }
    __syncthreads();

    for (int t = 0; t < nt; t++) {
        const int buf = t & 1;
        const bool more = (t + 1 < nt);
        float4 ra0, ra1, rb0, rb1;
        if (more) {
            int k0 = (t+1) << 4;
            ra0 = *(const float4*)&A[(size_t)(m0+am)*K + k0 + akc];
            ra1 = *(const float4*)&A[(size_t)(m0+am+64)*K + k0 + akc];
            rb0 = *(const float4*)&W[(size_t)(k0+bkr)*N + n0 + bnc];
            rb1 = *(const float4*)&W[(size_t)(k0+bkr+8)*N + n0 + bnc];
        }

        #pragma unroll
        for (int kk = 0; kk < 16; kk += 8) {
            uint32_t af[2][4];
            #pragma unroll
            for (int mi = 0; mi < 2; mi++) {
                int mb = warp_m + mi*16 + grp;
                af[mi][0] = __float_as_uint(As[buf][kk+qd  ][mb]);
                af[mi][1] = __float_as_uint(As[buf][kk+qd  ][mb+8]);
                af[mi][2] = __float_as_uint(As[buf][kk+qd+4][mb]);
                af[mi][3] = __float_as_uint(As[buf][kk+qd+4][mb+8]);
            }
            #pragma unroll
            for (int ni = 0; ni < 8; ni++) {
                int nb = warp_n + ni*8 + grp;
                uint32_t b0 = __float_as_uint(Bs[buf][kk+qd  ][nb]);
                uint32_t b1 = __float_as_uint(Bs[buf][kk+qd+4][nb]);
                mma_tf32(acc[0][ni], af[0], b0, b1);
                mma_tf32(acc[1][ni], af[1], b0, b1);
            }
        }

        if (more) {
            int nb = buf ^ 1;
            As[nb][akc+0][am] = to_tf32(ra0.x); As[nb][akc+1][am] = to_tf32(ra0.y);
            As[nb][akc+2][am] = to_tf32(ra0.z); As[nb][akc+3][am] = to_tf32(ra0.w);
            As[nb][akc+0][am+64] = to_tf32(ra1.x); As[nb][akc+1][am+64] = to_tf32(ra1.y);
            As[nb][akc+2][am+64] = to_tf32(ra1.z); As[nb][akc+3][am+64] = to_tf32(ra1.w);
            Bs[nb][bkr][bnc+0] = to_tf32(rb0.x); Bs[nb][bkr][bnc+1] = to_tf32(rb0.y);
            Bs[nb][bkr][bnc+2] = to_tf32(rb0.z); Bs[nb][bkr][bnc+3] = to_tf32(rb0.w);
            Bs[nb][bkr+8][bnc+0] = to_tf32(rb1.x); Bs[nb][bkr+8][bnc+1] = to_tf32(rb1.y);
            Bs[nb][bkr+8][bnc+2] = to_tf32(rb1.z); Bs[nb][bkr+8][bnc+3] = to_tf32(rb1.w);
        }
        __syncthreads();
    }

    // epilogue
    #pragma unroll
    for (int mi = 0; mi < 2; mi++) {
        int r0 = m0 + warp_m + mi*16 + grp;
        #pragma unroll
        for (int ni = 0; ni < 8; ni++) {
            int c = n0 + warp_n + ni*8 + qd*2;
            float b0 = bias[c], b1 = bias[c+1];
            float v0 = acc[mi][ni][0] + b0;
            float v1 = acc[mi][ni][1] + b1;
            float v2 = acc[mi][ni][2] + b0;
            float v3 = acc[mi][ni][3] + b1;
            if (resid) {
                v0 += resid[(size_t)r0*N + c];     v1 += resid[(size_t)r0*N + c + 1];
                v2 += resid[(size_t)(r0+8)*N + c]; v3 += resid[(size_t)(r0+8)*N + c + 1];
            }
            if (GELU) {
                v0 = 0.5f*v0*(1.0f + erff(v0*0.70710678118654752f));
                v1 = 0.5f*v1*(1.0f + erff(v1*0.70710678118654752f));
                v2 = 0.5f*v2*(1.0f + erff(v2*0.70710678118654752f));
                v3 = 0.5f*v3*(1.0f + erff(v3*0.70710678118654752f));
            }
            *(float2*)&C[(size_t)r0*N + c]     = make_float2(v0, v1);
            *(float2*)&C[(size_t)(r0+8)*N + c] = make_float2(v2, v3);
        }
    }
}

// ---------------------------------------------------------------------------
// Sampled sparsity measure M (one warp per (b,h,i))
// ---------------------------------------------------------------------------
__global__ void sampleM_kernel(const int* __restrict__ idxs) {
    int wg   = (blockIdx.x * blockDim.x + threadIdx.x) >> 5;
    int lane = threadIdx.x & 31;
    if (wg >= B_*NH*L_) return;
    int i = wg & (L_-1);
    int h = (wg >> 10) & (NH-1);
    int b = wg >> 13;
    const float* Qrow = &g_q[(size_t)(b*L_ + i)*DM + h*HD];
    float qa = Qrow[lane], qb = Qrow[lane+32];
    float mx = -FLT_MAX, sm = 0.f;
    for (int j = 0; j < SK; j++) {
        int s = idxs[i*SK + j];
        const float* Krow = &g_k[(size_t)(b*L_ + s)*DM + h*HD];
        float p = qa*Krow[lane] + qb*Krow[lane+32];
        #pragma unroll
        for (int o = 16; o > 0; o >>= 1) p += __shfl_xor_sync(0xffffffffu, p, o);
        mx = fmaxf(mx, p);
        sm += p;
    }
    if (lane == 0) g_M[(b*NH+h)*L_ + i] = mx - sm * (1.0f/SK);
}

// ---------------------------------------------------------------------------
// Exact top-35 (lowest-index tie-break). 1024 threads, value per thread.
// ---------------------------------------------------------------------------
__global__ void topk_kernel() {
    int bh = blockIdx.x;
    int t  = threadIdx.x;
    int lane = t & 31, w = t >> 5;
    float v = g_M[bh*L_ + t];
    __shared__ float wv[32];
    __shared__ int   wi[32];
    __shared__ int   win;
    for (int iter = 0; iter < SK; iter++) {
        float bv = v; int bi = t;
        #pragma unroll
        for (int o = 16; o > 0; o >>= 1) {
            float ov = __shfl_xor_sync(0xffffffffu, bv, o);
            int   oi = __shfl_xor_sync(0xffffffffu, bi, o);
            if (ov > bv || (ov == bv && oi < bi)) { bv = ov; bi = oi; }
        }
        if (lane == 0) { wv[w] = bv; wi[w] = bi; }
        __syncthreads();
        if (w == 0) {
            float bv2 = wv[lane]; int bi2 = wi[lane];
            #pragma unroll
            for (int o = 16; o > 0; o >>= 1) {
                float ov = __shfl_xor_sync(0xffffffffu, bv2, o);
                int   oi = __shfl_xor_sync(0xffffffffu, bi2, o);
                if (ov > bv2 || (ov == bv2 && oi < bi2)) { bv2 = ov; bi2 = oi; }
            }
            if (lane == 0) { win = bi2; g_top[bh*SK + iter] = bi2; }
        }
        __syncthreads();
        if (t == win) v = -FLT_MAX;
    }
}

// ---------------------------------------------------------------------------
// Fused attention per (b,h): vmean + broadcast fill + scores + softmax + ctx
// Grid = 32 blocks, 512 threads, ~187KB dynamic smem.
// ---------------------------------------------------------------------------
#define ATT_THREADS 512
#define SQ_ROWS 48
#define ATT_SMEM_FLOATS (35*1024 + SQ_ROWS*64 + 64*129 + 64 + 512 + 64)

__global__ void __launch_bounds__(ATT_THREADS, 1)
attn_fused() {
    extern __shared__ float dsm[];
    float* scores = dsm;                          // 35*1024
    float* sq     = scores + 35*1024;             // 48*64
    float* kt     = sq + SQ_ROWS*64;              // 64*129 (transposed tiles)
    float* vmean  = kt + 64*129;                  // 64
    float* red    = vmean + 64;                   // 512
    int*   tops   = (int*)(red + 512);            // 48

    const int bh = blockIdx.x;
    const int b  = bh >> 3;
    const int h  = bh & 7;
    const int t  = threadIdx.x;
    const int lane = t & 31;
    const int w  = t >> 5;                        // 0..15

    if (t < SK) tops[t] = g_top[bh*SK + t];
    __syncthreads();

    // load selected Q rows (pad rows >= SK with 0)
    for (int f = t; f < SQ_ROWS*64; f += ATT_THREADS) {
        int u = f >> 6, k = f & 63;
        sq[f] = (u < SK) ? g_q[(size_t)((b<<10) + tops[u])*DM + h*HD + k] : 0.f;
    }

    // vmean over V rows
    {
        int e = t & 63, r = t >> 6;               // 8 chunks of 128 rows
        float acc = 0.f;
        for (int l = r*128; l < r*128 + 128; l++)
            acc += g_v[(size_t)((b<<10) + l)*DM + h*HD + e];
        red[t] = acc;
        __syncthreads();
        if (t < 64) {
            float s = 0.f;
            #pragma unroll
            for (int rr = 0; rr < 8; rr++) s += red[t + rr*64];
            vmean[t] = s * (1.0f/L_);
        }
        __syncthreads();
    }

    // broadcast fill of ctx (float4)
    {
        const float4* vm4 = (const float4*)vmean;
        for (int f = t; f < (L_*HD)/4; f += ATT_THREADS) {
            int l = f >> 4, ev = f & 15;
            *(float4*)&g_ctx[(size_t)((b<<10) + l)*DM + h*HD + ev*4] = vm4[ev];
        }
    }

    // scores: loop s-tiles of 128, K staged transposed kt[e][s] (stride 129)
    for (int st = 0; st < 8; st++) {
        #pragma unroll
        for (int i = 0; i < 4; i++) {
            int f = t + i*ATT_THREADS;            // 0..2047 float4s
            int s = f >> 4, ec = (f & 15) << 2;
            float4 kv = *(const float4*)&g_k[(size_t)((b<<10) + st*128 + s)*DM + h*HD + ec];
            kt[(ec+0)*129 + s] = kv.x;
            kt[(ec+1)*129 + s] = kv.y;
            kt[(ec+2)*129 + s] = kv.z;
            kt[(ec+3)*129 + s] = kv.w;
        }
        __syncthreads();

        float acc[3][4];
        #pragma unroll
        for (int uu = 0; uu < 3; uu++)
            #pragma unroll
            for (int j = 0; j < 4; j++) acc[uu][j] = 0.f;

        for (int k = 0; k < 64; k++) {
            float kv0 = kt[k*129 + lane];
            float kv1 = kt[k*129 + lane + 32];
            float kv2 = kt[k*129 + lane + 64];
            float kv3 = kt[k*129 + lane + 96];
            #pragma unroll
            for (int uu = 0; uu < 3; uu++) {
                float qv = sq[(uu*16 + w)*64 + k];
                acc[uu][0] += qv*kv0; acc[uu][1] += qv*kv1;
                acc[uu][2] += qv*kv2; acc[uu][3] += qv*kv3;
            }
        }
        #pragma unroll
        for (int uu = 0; uu < 3; uu++) {
            int u = uu*16 + w;
            if (u < SK) {
                scores[u*1024 + st*128 + lane]      = acc[uu][0]*0.125f;
                scores[u*1024 + st*128 + lane + 32] = acc[uu][1]*0.125f;
                scores[u*1024 + st*128 + lane + 64] = acc[uu][2]*0.125f;
                scores[u*1024 + st*128 + lane + 96] = acc[uu][3]*0.125f;
            }
        }
        __syncthreads();
    }

    // softmax rows (warp per row)
    for (int u = w; u < SK; u += 16) {
        float* row = &scores[u*1024];
        float m = -FLT_MAX;
        #pragma unroll
        for (int i = 0; i < 32; i++) m = fmaxf(m, row[lane + 32*i]);
        #pragma unroll
        for (int o = 16; o > 0; o >>= 1) m = fmaxf(m, __shfl_xor_sync(0xffffffffu, m, o));
        float s = 0.f;
        #pragma unroll
        for (int i = 0; i < 32; i++) {
            float e = expf(row[lane + 32*i] - m);
            row[lane + 32*i] = e;
            s += e;
        }
        #pragma unroll
        for (int o = 16; o > 0; o >>= 1) s += __shfl_xor_sync(0xffffffffu, s, o);
        float inv = 1.0f / s;
        #pragma unroll
        for (int i = 0; i < 32; i++) row[lane + 32*i] *= inv;
    }
    __syncthreads();

    // ctx = probs @ V, V staged transposed in kt
    {
        int e = t & 63, ug = t >> 6;              // ug 0..7
        float acc9[5] = {0.f, 0.f, 0.f, 0.f, 0.f};
        for (int st = 0; st < 8; st++) {
            #pragma unroll
            for (int i = 0; i < 4; i++) {
                int f = t + i*ATT_THREADS;
                int s = f >> 4, ec = (f & 15) << 2;
                float4 vv = *(const float4*)&g_v[(size_t)((b<<10) + st*128 + s)*DM + h*HD + ec];
                kt[(ec+0)*129 + s] = vv.x;
                kt[(ec+1)*129 + s] = vv.y;
                kt[(ec+2)*129 + s] = vv.z;
                kt[(ec+3)*129 + s] = vv.w;
            }
            __syncthreads();
            for (int s = 0; s < 128; s++) {
                float v = kt[e*129 + s];
                #pragma unroll
                for (int uu = 0; uu < 5; uu++) {
                    int u = ug + (uu << 3);
                    if (u < SK) acc9[uu] += scores[u*1024 + st*128 + s] * v;
                }
            }
            __syncthreads();
        }
        #pragma unroll
        for (int uu = 0; uu < 5; uu++) {
            int u = ug + (uu << 3);
            if (u < SK) {
                int qi = tops[u];
                g_ctx[(size_t)((b<<10) + qi)*DM + h*HD + e] = acc9[uu];
            }
        }
    }
}

// ---------------------------------------------------------------------------
// LayerNorm (row of 512, 256 threads)
// ---------------------------------------------------------------------------
__global__ void ln_kernel(const float* __restrict__ in, float* __restrict__ out,
                          const float* __restrict__ g, const float* __restrict__ be) {
    int row = blockIdx.x;
    int t   = threadIdx.x;
    float v0 = in[(size_t)row*DM + t];
    float v1 = in[(size_t)row*DM + t + 256];
    __shared__ float red[256];
    red[t] = v0 + v1; __syncthreads();
    for (int s = 128; s > 0; s >>= 1) { if (t < s) red[t] += red[t+s]; __syncthreads(); }
    float mean = red[0] * (1.0f/DM);
    __syncthreads();
    float d0 = v0 - mean, d1 = v1 - mean;
    red[t] = d0*d0 + d1*d1; __syncthreads();
    for (int s = 128; s > 0; s >>= 1) { if (t < s) red[t] += red[t+s]; __syncthreads(); }
    float rstd = rsqrtf(red[0] * (1.0f/DM) + 1e-5f);
    out[(size_t)row*DM + t]       = d0*rstd*g[t]     + be[t];
    out[(size_t)row*DM + t + 256] = d1*rstd*g[t+256] + be[t+256];
}

// ---------------------------------------------------------------------------
// Mean pool + classifier
// ---------------------------------------------------------------------------
__global__ void pool1_kernel() {
    int b = blockIdx.x, r = blockIdx.y;
    int d = threadIdx.x;
    float acc = 0.f;
    for (int l = r*128; l < r*128 + 128; l++)
        acc += g_tmp[(size_t)(b*L_+l)*DM + d];
    g_poolp[(b*8 + r)*DM + d] = acc;
}

__global__ void pool2_kernel() {
    int b = blockIdx.x;
    int d = threadIdx.x;
    float acc = 0.f;
    #pragma unroll
    for (int r = 0; r < 8; r++) acc += g_poolp[(b*8 + r)*DM + d];
    g_pool[b*DM + d] = acc * (1.0f/L_);
}

__global__ void cls_kernel(const float* __restrict__ Wc,
                           const float* __restrict__ bc,
                           float* __restrict__ out) {
    int t = threadIdx.x;
    if (t >= B_*10) return;
    int b = t / 10, c = t % 10;
    float acc = bc[c];
    for (int d = 0; d < DM; d++) acc += g_pool[b*DM + d] * Wc[d*10 + c];
    out[b*10 + c] = acc;
}

// ---------------------------------------------------------------------------
extern "C" void kernel_launch(void* const* d_in, const int* in_sizes, int n_in,
                              void* d_out, int out_size) {
    const float* src   = (const float*)d_in[0];
    const int*   idxs  = (const int*)  d_in[1];
    const float* Wemb  = (const float*)d_in[2];
    const float* bemb  = (const float*)d_in[3];
    const float* Wq    = (const float*)d_in[4];
    const float* bq    = (const float*)d_in[5];
    const float* Wk    = (const float*)d_in[6];
    const float* bk    = (const float*)d_in[7];
    const float* Wv    = (const float*)d_in[8];
    const float* bv    = (const float*)d_in[9];
    const float* Wo    = (const float*)d_in[10];
    const float* bo    = (const float*)d_in[11];
    const float* g1    = (const float*)d_in[12];
    const float* beta1 = (const float*)d_in[13];
    const float* W1    = (const float*)d_in[14];
    const float* bf1   = (const float*)d_in[15];
    const float* W2    = (const float*)d_in[16];
    const float* bf2   = (const float*)d_in[17];
    const float* g2    = (const float*)d_in[18];
    const float* beta2 = (const float*)d_in[19];
    const float* gf    = (const float*)d_in[20];
    const float* betaf = (const float*)d_in[21];
    const float* Wc    = (const float*)d_in[22];
    const float* bc    = (const float*)d_in[23];

    void *px_, *ptmp_, *pq_, *pk_, *pv_, *pctx_, *pff_;
    cudaGetSymbolAddress(&px_,   g_x);
    cudaGetSymbolAddress(&ptmp_, g_tmp);
    cudaGetSymbolAddress(&pq_,   g_q);
    cudaGetSymbolAddress(&pk_,   g_k);
    cudaGetSymbolAddress(&pv_,   g_v);
    cudaGetSymbolAddress(&pctx_, g_ctx);
    cudaGetSymbolAddress(&pff_,  g_ff);
    float* px   = (float*)px_;
    float* ptmp = (float*)ptmp_;
    float* pq   = (float*)pq_;
    float* pk   = (float*)pk_;
    float* pv   = (float*)pv_;
    float* pctx = (float*)pctx_;
    float* pff  = (float*)pff_;

    const int attn_smem = ATT_SMEM_FLOATS * 4;
    cudaFuncSetAttribute(attn_fused, cudaFuncAttributeMaxDynamicSharedMemorySize, attn_smem);

    embed_kernel<<<NTOK, 512>>>(src, Wemb, bemb);

    for (int l = 0; l < 2; l++) {
        const float* Wq_l = Wq + (size_t)l*DM*DM;
        const float* Wk_l = Wk + (size_t)l*DM*DM;
        const float* Wv_l = Wv + (size_t)l*DM*DM;
        const float* Wo_l = Wo + (size_t)l*DM*DM;
        const float* W1_l = W1 + (size_t)l*DM*DFF;
        const float* W2_l = W2 + (size_t)l*DFF*DM;

        dim3 gDM(DM/128, NTOK/128);     // (4, 32)
        dim3 gFF(DFF/128, NTOK/128);    // (16, 32)

        gemm_tc<false><<<gDM, 256>>>(px, Wq_l, bq + l*DM, nullptr, pq, DM, DM);
        gemm_tc<false><<<gDM, 256>>>(px, Wk_l, bk + l*DM, nullptr, pk, DM, DM);
        gemm_tc<false><<<gDM, 256>>>(px, Wv_l, bv + l*DM, nullptr, pv, DM, DM);

        sampleM_kernel<<<(B_*NH*L_)/4, 128>>>(idxs + (size_t)l*L_*SK);
        topk_kernel<<<B_*NH, 1024>>>();
        attn_fused<<<B_*NH, ATT_THREADS, attn_smem>>>();

        gemm_tc<false><<<gDM, 256>>>(pctx, Wo_l, bo + l*DM, px, ptmp, DM, DM);
        ln_kernel<<<NTOK, 256>>>(ptmp, px, g1 + l*DM, beta1 + l*DM);

        gemm_tc<true ><<<gFF, 256>>>(px, W1_l, bf1 + l*DFF, nullptr, pff, DFF, DM);
        gemm_tc<false><<<gDM, 256>>>(pff, W2_l, bf2 + l*DM, px, ptmp, DM, DFF);
        ln_kernel<<<NTOK, 256>>>(ptmp, px, g2 + l*DM, beta2 + l*DM);
    }

    ln_kernel<<<NTOK, 256>>>(px, ptmp, gf, betaf);
    pool1_kernel<<<dim3(B_, 8), 512>>>();
    pool2_kernel<<<B_, 512>>>();
    cls_kernel<<<1, 64>>>(Wc, bc, (float*)d_out);
}